// round 15
// baseline (speedup 1.0000x reference)
#include <cuda_runtime.h>

#define H 128
#define W 128
#define NCONV 8
#define TILE_ROWS 8
#define FROWS 10          // TILE_ROWS + 2 halo
#define ESTRIDE 66        // entries per (f,row) in Pe/Po (65/64 used, padded)
#define NTHREADS 256
#define NWARP 8
#define NTASK (FROWS * 5) // 50 feature tasks

// dynamic smem layout (bytes) — j0-3 weights in __constant__, j4-7 in smem
#define OFF_PE   0                                   // ull Pe[4][10][66] = 21120  (P[2m])
#define OFF_PO   21120                               // ull Po[4][10][66] = 21120  (P[2m+1])
#define OFF_W4   42240                               // ull ws4[144]      = 1152   (j4..7)
#define SMEM_BYTES 43392

typedef unsigned long long ull;

__device__ __forceinline__ ull pk2(float lo, float hi) {
    ull r; asm("mov.b64 %0, {%1, %2};" : "=l"(r) : "f"(lo), "f"(hi)); return r;
}
__device__ __forceinline__ void fma2(ull &d, ull a, ull b) {
    asm("fma.rn.f32x2 %0, %1, %2, %0;" : "+l"(d) : "l"(a), "l"(b));
}
__device__ __forceinline__ float tanh_ap(float x) {
    float r; asm("tanh.approx.f32 %0, %1;" : "=f"(r) : "f"(x)); return r;
}

// constant bank: [0..287] dup-pair weights [(tap*4+f)*8+j], [288..295] bias
__constant__ ull cw[296];
__device__   ull g_wstage[296];

// features of one input value: 2 MUFU + a few fma
__device__ __forceinline__ void feats(float xv, float &s, float &t, float &t2, float &t3) {
    t = tanh_ap(xv);                               // tanh
    float th = tanh_ap(0.5f * xv);
    float sg = fmaf(0.5f, th, 0.5f);               // sigmoid(x)
    s  = xv * sg;                                  // silu
    t2 = fmaf(t + t, t, -1.f);                     // T2
    t3 = fmaf(t + t, t2, -t);                      // T3
}

__global__ void prep_kernel(const float* __restrict__ cheby,
                            const float* __restrict__ bw,
                            const float* __restrict__ ss) {
    int idx = threadIdx.x;
    if (idx < 288) {
        int j   = idx & 7;
        int fi  = idx >> 3;
        int tap = fi >> 2;
        int f   = fi & 3;
        float wv;
        if (f == 0) wv = bw[j * 9 + tap];
        else        wv = cheby[(j * 9 + tap) * 4 + f] * ss[j * 9 + tap];
        g_wstage[idx] = pk2(wv, wv);
    } else if (idx < 296) {
        int j = idx - 288;
        float sum = 0.f;
        #pragma unroll
        for (int i = 0; i < 9; i++) sum += cheby[(j * 9 + i) * 4] * ss[j * 9 + i];
        g_wstage[idx] = pk2(sum, sum);
    }
}

__global__ void __launch_bounds__(NTHREADS, 5)
kan_conv_kernel(const float* __restrict__ x, float* __restrict__ out)
{
    extern __shared__ char smem_raw[];
    ull* Pe  = (ull*)(smem_raw + OFF_PE);     // P[2m]   = (F(2m),   F(2m+1))
    ull* Po  = (ull*)(smem_raw + OFF_PO);     // P[2m+1] = (F(2m+1), F(2m+2))
    ull* ws4 = (ull*)(smem_raw + OFF_W4);     // j4..7 dup pairs: [fi*4 + (j-4)]

    const int tid  = threadIdx.x;
    const int wid  = tid >> 5;
    const int lane = tid & 31;
    const int blk  = blockIdx.x;
    const int bc   = blk >> 4;                    // plane b*C + c (0..255)
    const int r0   = (blk & 15) * TILE_ROWS;      // tile top row

    const float* xp = x + (size_t)bc * (H * W);

    // ---- Phase B1: prefetch all feature-input LDGs (MLP up to 7 per warp) ----
    float xv[7];
    {
        int row = (wid >= 5) ? 1 : 0;
        int c   = wid - ((wid >= 5) ? 5 : 0);
        #pragma unroll
        for (int q = 0; q < 7; q++) {
            int gr  = r0 - 1 + row;
            int col = ((c << 5) - c) + lane - 1;   // c*31 + lane - 1
            xv[q] = 0.f;
            if ((wid + q * 8 < NTASK) & ((unsigned)gr < H) & ((unsigned)col < W))
                xv[q] = xp[(gr << 7) + col];       // W == 128
            row += 1; c += 3;
            if (c >= 5) { c -= 5; row += 1; }
        }
    }

    // ---- stage j4..7 weights into smem (1 LDG/thread, L2-hit; covers B1) ----
    if (tid < 144) {
        ws4[tid] = g_wstage[((tid >> 2) << 3) + 4 + (tid & 3)];
    }

    // ---- Phase B2: features -> parity-split pair smem, conflict-free ----
    {
        int c    = wid - ((wid >= 5) ? 5 : 0);
        int rowE = (wid >= 5) ? ESTRIDE : 0;       // row * ESTRIDE, incremental
        #pragma unroll
        for (int q = 0; q < 7; q++) {
            if (wid + q * 8 < NTASK) {             // warp-uniform
                int i = ((c << 5) - c) + lane;     // feature index (col = i-1)
                float s, t1, t2, t3;
                feats(xv[q], s, t1, t2, t3);       // x=0 padding -> (0,0,-1,0) ✓
                float ps  = __shfl_up_sync(0xffffffffu, s,  1);
                float pt  = __shfl_up_sync(0xffffffffu, t1, 1);
                float pt2 = __shfl_up_sync(0xffffffffu, t2, 1);
                float pt3 = __shfl_up_sync(0xffffffffu, t3, 1);
                int k = i - 1;
                if (lane >= 1 && k <= 128) {
                    int rb = rowE + (k >> 1);
                    ull v0 = pk2(ps,  s);
                    ull v1 = pk2(pt,  t1);
                    ull v2 = pk2(pt2, t2);
                    ull v3 = pk2(pt3, t3);
                    if ((k & 1) == 0) {
                        Pe[(0 * FROWS) * ESTRIDE + rb] = v0;
                        Pe[(1 * FROWS) * ESTRIDE + rb] = v1;
                        Pe[(2 * FROWS) * ESTRIDE + rb] = v2;
                        Pe[(3 * FROWS) * ESTRIDE + rb] = v3;
                    } else {
                        Po[(0 * FROWS) * ESTRIDE + rb] = v0;
                        Po[(1 * FROWS) * ESTRIDE + rb] = v1;
                        Po[(2 * FROWS) * ESTRIDE + rb] = v2;
                        Po[(3 * FROWS) * ESTRIDE + rb] = v3;
                    }
                }
            }
            c += 3;
            if (c >= 5) { c -= 5; rowE += 2 * ESTRIDE; } else { rowE += ESTRIDE; }
        }
    }
    __syncthreads();

    // ---- Compute: thread -> 2 output rows (ty, ty+1), cols {2L, 2L+1}, 8 j ----
    // Weight reads split across ports: j0..3 constant (LDC), j4..7 smem (LDS).
    const int L  = tid & 63;                       // col-pair index, c0 = 2L
    const int ty = (tid >> 6) * 2;                 // local out rows ty, ty+1

    ull acc[8][2];                                 // [j][r]
    #pragma unroll
    for (int j = 0; j < 8; j++) {
        ull b = cw[288 + j];
        acc[j][0] = b; acc[j][1] = b;
    }

    const int tybase = ty * ESTRIDE + L;           // single IMAD; rest immediates

    #pragma unroll
    for (int f = 0; f < 4; f++) {
        ull lo[3], hi[3];
        {   // input rows ty (lo) and ty+1 (hi)
            int b0 = (f * FROWS) * ESTRIDE + tybase;
            lo[0] = Pe[b0]; lo[1] = Po[b0]; lo[2] = Pe[b0 + 1];
            int b1 = b0 + ESTRIDE;
            hi[0] = Pe[b1]; hi[1] = Po[b1]; hi[2] = Pe[b1 + 1];
        }
        #pragma unroll
        for (int dy = 0; dy < 3; dy++) {
            #pragma unroll
            for (int dx = 0; dx < 3; dx++) {
                const int fi = (dy * 3 + dx) * 4 + f;
                ull f0 = lo[dx];                   // feeds out row ty
                ull f1 = hi[dx];                   // feeds out row ty+1
                {   // j 0..3 : constant port
                    const ulonglong2* wp = (const ulonglong2*)&cw[fi * 8];
                    ulonglong2 w01 = wp[0], w23 = wp[1];
                    fma2(acc[0][0], f0, w01.x); fma2(acc[0][1], f1, w01.x);
                    fma2(acc[1][0], f0, w01.y); fma2(acc[1][1], f1, w01.y);
                    fma2(acc[2][0], f0, w23.x); fma2(acc[2][1], f1, w23.x);
                    fma2(acc[3][0], f0, w23.y); fma2(acc[3][1], f1, w23.y);
                }
                {   // j 4..7 : l1tex port (broadcast LDS.128)
                    const ulonglong2* sp = (const ulonglong2*)&ws4[fi * 4];
                    ulonglong2 w45 = sp[0], w67 = sp[1];
                    fma2(acc[4][0], f0, w45.x); fma2(acc[4][1], f1, w45.x);
                    fma2(acc[5][0], f0, w45.y); fma2(acc[5][1], f1, w45.y);
                    fma2(acc[6][0], f0, w67.x); fma2(acc[6][1], f1, w67.x);
                    fma2(acc[7][0], f0, w67.y); fma2(acc[7][1], f1, w67.y);
                }
            }
            if (dy < 2) {                          // roll window: lo <- hi, next row
                lo[0] = hi[0]; lo[1] = hi[1]; lo[2] = hi[2];
                int bn = (f * FROWS + dy + 2) * ESTRIDE + tybase;
                hi[0] = Pe[bn]; hi[1] = Po[bn]; hi[2] = Pe[bn + 1];
            }
        }
    }

    // ---- stores: STG.64, dense per warp ----
    float* ob = out + ((size_t)(bc * NCONV) * H + (r0 + ty)) * W + 2 * L;
    #pragma unroll
    for (int j = 0; j < 8; j++) {
        #pragma unroll
        for (int r = 0; r < 2; r++) {
            *(ull*)(ob + (size_t)j * (H * W) + r * W) = acc[j][r];
        }
    }
}

extern "C" void kernel_launch(void* const* d_in, const int* in_sizes, int n_in,
                              void* d_out, int out_size) {
    const float* x     = (const float*)d_in[0];
    const float* cheby = (const float*)d_in[1];   // (8, 9, 4)
    const float* bw    = (const float*)d_in[2];   // (8, 9)
    const float* ss    = (const float*)d_in[3];   // (8, 9)
    float* out = (float*)d_out;

    cudaFuncSetAttribute(kan_conv_kernel,
                         cudaFuncAttributeMaxDynamicSharedMemorySize, SMEM_BYTES);

    // 1) compute dup-pair weights into staging, 2) copy into __constant__ bank
    //    (D2D async memcpy — graph-capturable), 3) main kernel reads via LDC/LDS.
    prep_kernel<<<1, 296>>>(cheby, bw, ss);
    void* stage_ptr = nullptr;
    cudaGetSymbolAddress(&stage_ptr, g_wstage);
    cudaMemcpyToSymbolAsync(cw, stage_ptr, 296 * sizeof(ull), 0,
                            cudaMemcpyDeviceToDevice, 0);

    const int planes = 16 * 16;                   // B * C
    dim3 grid(planes * (H / TILE_ROWS));          // 4096 blocks
    kan_conv_kernel<<<grid, NTHREADS, SMEM_BYTES>>>(x, out);
}

// round 16
// speedup vs baseline: 1.4938x; 1.4938x over previous
#include <cuda_runtime.h>

#define H 128
#define W 128
#define NCONV 8
#define TILE_ROWS 8
#define FROWS 10          // TILE_ROWS + 2 halo
#define ESTRIDE 66        // entries per (f,row) in Pe/Po (65/64 used, padded)
#define NTHREADS 256
#define NWARP 8
#define NTASK (FROWS * 5) // 50 feature tasks

// dynamic smem layout (bytes) — weights/bias in __constant__
#define OFF_PE   0                                   // ull Pe[4][10][66] = 21120  (P[2m])
#define OFF_PO   21120                               // ull Po[4][10][66] = 21120  (P[2m+1])
#define SMEM_BYTES 42240

typedef unsigned long long ull;

__device__ __forceinline__ ull pk2(float lo, float hi) {
    ull r; asm("mov.b64 %0, {%1, %2};" : "=l"(r) : "f"(lo), "f"(hi)); return r;
}
__device__ __forceinline__ void fma2(ull &d, ull a, ull b) {
    asm("fma.rn.f32x2 %0, %1, %2, %0;" : "+l"(d) : "l"(a), "l"(b));
}
__device__ __forceinline__ float tanh_ap(float x) {
    float r; asm("tanh.approx.f32 %0, %1;" : "=f"(r) : "f"(x)); return r;
}

// constant bank: [0..287] dup-pair weights [(tap*4+f)*8+j], [288..295] bias
__constant__ ull cw[296];
__device__   ull g_wstage[296];

// features of one input value: 2 MUFU + a few fma
__device__ __forceinline__ void feats(float xv, float &s, float &t, float &t2, float &t3) {
    t = tanh_ap(xv);                               // tanh
    float th = tanh_ap(0.5f * xv);
    float sg = fmaf(0.5f, th, 0.5f);               // sigmoid(x)
    s  = xv * sg;                                  // silu
    t2 = fmaf(t + t, t, -1.f);                     // T2
    t3 = fmaf(t + t, t2, -t);                      // T3
}

__global__ void prep_kernel(const float* __restrict__ cheby,
                            const float* __restrict__ bw,
                            const float* __restrict__ ss) {
    int idx = threadIdx.x;
    if (idx < 288) {
        int j   = idx & 7;
        int fi  = idx >> 3;
        int tap = fi >> 2;
        int f   = fi & 3;
        float wv;
        if (f == 0) wv = bw[j * 9 + tap];
        else        wv = cheby[(j * 9 + tap) * 4 + f] * ss[j * 9 + tap];
        g_wstage[idx] = pk2(wv, wv);
    } else if (idx < 296) {
        int j = idx - 288;
        float sum = 0.f;
        #pragma unroll
        for (int i = 0; i < 9; i++) sum += cheby[(j * 9 + i) * 4] * ss[j * 9 + i];
        g_wstage[idx] = pk2(sum, sum);
    }
}

__global__ void __launch_bounds__(NTHREADS, 4)
kan_conv_kernel(const float* __restrict__ x, float* __restrict__ out)
{
    extern __shared__ char smem_raw[];
    ull* Pe = (ull*)(smem_raw + OFF_PE);      // P[2m]   = (F(2m),   F(2m+1))
    ull* Po = (ull*)(smem_raw + OFF_PO);      // P[2m+1] = (F(2m+1), F(2m+2))

    const int tid  = threadIdx.x;
    const int wid  = tid >> 5;
    const int lane = tid & 31;
    const int blk  = blockIdx.x;
    const int bc   = blk >> 4;                    // plane b*C + c (0..255)
    const int r0   = (blk & 15) * TILE_ROWS;      // tile top row

    const float* xp = x + (size_t)bc * (H * W);

    // ---- Phase B1: prefetch all feature-input LDGs (MLP up to 7 per warp) ----
    float xv[7];
    {
        int row = (wid >= 5) ? 1 : 0;
        int c   = wid - ((wid >= 5) ? 5 : 0);
        #pragma unroll
        for (int q = 0; q < 7; q++) {
            int gr  = r0 - 1 + row;
            int col = ((c << 5) - c) + lane - 1;   // c*31 + lane - 1
            xv[q] = 0.f;
            if ((wid + q * 8 < NTASK) & ((unsigned)gr < H) & ((unsigned)col < W))
                xv[q] = xp[(gr << 7) + col];       // W == 128
            row += 1; c += 3;
            if (c >= 5) { c -= 5; row += 1; }
        }
    }

    // ---- Phase B2: features -> parity-split pair smem, conflict-free ----
    {
        int c    = wid - ((wid >= 5) ? 5 : 0);
        int rowE = (wid >= 5) ? ESTRIDE : 0;       // row * ESTRIDE, incremental
        #pragma unroll
        for (int q = 0; q < 7; q++) {
            if (wid + q * 8 < NTASK) {             // warp-uniform
                int i = ((c << 5) - c) + lane;     // feature index (col = i-1)
                float s, t1, t2, t3;
                feats(xv[q], s, t1, t2, t3);       // x=0 padding -> (0,0,-1,0) ✓
                float ps  = __shfl_up_sync(0xffffffffu, s,  1);
                float pt  = __shfl_up_sync(0xffffffffu, t1, 1);
                float pt2 = __shfl_up_sync(0xffffffffu, t2, 1);
                float pt3 = __shfl_up_sync(0xffffffffu, t3, 1);
                int k = i - 1;
                if (lane >= 1 && k <= 128) {
                    int rb = rowE + (k >> 1);
                    ull v0 = pk2(ps,  s);
                    ull v1 = pk2(pt,  t1);
                    ull v2 = pk2(pt2, t2);
                    ull v3 = pk2(pt3, t3);
                    if ((k & 1) == 0) {
                        Pe[(0 * FROWS) * ESTRIDE + rb] = v0;
                        Pe[(1 * FROWS) * ESTRIDE + rb] = v1;
                        Pe[(2 * FROWS) * ESTRIDE + rb] = v2;
                        Pe[(3 * FROWS) * ESTRIDE + rb] = v3;
                    } else {
                        Po[(0 * FROWS) * ESTRIDE + rb] = v0;
                        Po[(1 * FROWS) * ESTRIDE + rb] = v1;
                        Po[(2 * FROWS) * ESTRIDE + rb] = v2;
                        Po[(3 * FROWS) * ESTRIDE + rb] = v3;
                    }
                }
            }
            c += 3;
            if (c >= 5) { c -= 5; rowE += 2 * ESTRIDE; } else { rowE += ESTRIDE; }
        }
    }
    __syncthreads();

    // ---- Compute (Config C): thread -> 4 j (jbase..jbase+3), 2 rows, 4 cols ----
    // L' = col quad (cols 4L'..4L'+3); b = row*ESTRIDE + 2L' is EVEN ->
    // LDS.128 on Pe gives (P[4L'],P[4L'+2]), on Po gives (P[4L'+1],P[4L'+3]),
    // LDS.64 Pe[b+2] gives P[4L'+4]: 5 pairs serving both column pairs.
    const int Lq    = tid & 31;                    // col-quad index
    const int ty    = ((tid >> 5) & 3) * 2;        // local out rows ty, ty+1
    const int jbase = (tid >> 7) * 4;              // j group: 0..3 or 4..7

    ull acc[4][2][2];                              // [jj][r][g]  g=col-pair
    #pragma unroll
    for (int jj = 0; jj < 4; jj++) {
        ull b = cw[288 + jbase + jj];
        acc[jj][0][0] = b; acc[jj][0][1] = b;
        acc[jj][1][0] = b; acc[jj][1][1] = b;
    }

    const int tybase = ty * ESTRIDE + 2 * Lq;      // even -> 16B-aligned LDS.128
    const int cwoff  = jbase;                      // cw index offset for j group

    #pragma unroll
    for (int f = 0; f < 4; f++) {
        // rolling 2-row window: 5 pairs per row
        ull lo[5], hi[5];
        {
            int b0 = (f * FROWS) * ESTRIDE + tybase;
            ulonglong2 pe = *(const ulonglong2*)&Pe[b0];
            ulonglong2 po = *(const ulonglong2*)&Po[b0];
            lo[0] = pe.x; lo[1] = po.x; lo[2] = pe.y; lo[3] = po.y; lo[4] = Pe[b0 + 2];
            int b1 = b0 + ESTRIDE;
            ulonglong2 pe1 = *(const ulonglong2*)&Pe[b1];
            ulonglong2 po1 = *(const ulonglong2*)&Po[b1];
            hi[0] = pe1.x; hi[1] = po1.x; hi[2] = pe1.y; hi[3] = po1.y; hi[4] = Pe[b1 + 2];
        }
        #pragma unroll
        for (int dy = 0; dy < 3; dy++) {
            #pragma unroll
            for (int dx = 0; dx < 3; dx++) {
                const int fi = (dy * 3 + dx) * 4 + f;
                const ulonglong2* wp = (const ulonglong2*)&cw[fi * 8 + cwoff];
                ulonglong2 wA = wp[0], wB = wp[1];     // j jbase..jbase+3
                ull l0 = lo[dx], l1 = lo[dx + 2];      // row ty+dy, col pairs
                ull h0 = hi[dx], h1 = hi[dx + 2];      // row ty+1+dy
                fma2(acc[0][0][0], l0, wA.x); fma2(acc[0][0][1], l1, wA.x);
                fma2(acc[0][1][0], h0, wA.x); fma2(acc[0][1][1], h1, wA.x);
                fma2(acc[1][0][0], l0, wA.y); fma2(acc[1][0][1], l1, wA.y);
                fma2(acc[1][1][0], h0, wA.y); fma2(acc[1][1][1], h1, wA.y);
                fma2(acc[2][0][0], l0, wB.x); fma2(acc[2][0][1], l1, wB.x);
                fma2(acc[2][1][0], h0, wB.x); fma2(acc[2][1][1], h1, wB.x);
                fma2(acc[3][0][0], l0, wB.y); fma2(acc[3][0][1], l1, wB.y);
                fma2(acc[3][1][0], h0, wB.y); fma2(acc[3][1][1], h1, wB.y);
            }
            if (dy < 2) {                          // roll: lo <- hi, load next row
                lo[0] = hi[0]; lo[1] = hi[1]; lo[2] = hi[2]; lo[3] = hi[3]; lo[4] = hi[4];
                int bn = (f * FROWS + dy + 2) * ESTRIDE + tybase;
                ulonglong2 pen = *(const ulonglong2*)&Pe[bn];
                ulonglong2 pon = *(const ulonglong2*)&Po[bn];
                hi[0] = pen.x; hi[1] = pon.x; hi[2] = pen.y; hi[3] = pon.y; hi[4] = Pe[bn + 2];
            }
        }
    }

    // ---- stores: 8 x STG.128 (16B aligned: col 4L' * 4B), coalesced ----
    float* ob = out + ((size_t)(bc * NCONV + jbase) * H + (r0 + ty)) * W + 4 * Lq;
    #pragma unroll
    for (int jj = 0; jj < 4; jj++) {
        #pragma unroll
        for (int r = 0; r < 2; r++) {
            ulonglong2 v; v.x = acc[jj][r][0]; v.y = acc[jj][r][1];
            *(ulonglong2*)(ob + ((size_t)jj * H + r) * W) = v;
        }
    }
}

extern "C" void kernel_launch(void* const* d_in, const int* in_sizes, int n_in,
                              void* d_out, int out_size) {
    const float* x     = (const float*)d_in[0];
    const float* cheby = (const float*)d_in[1];   // (8, 9, 4)
    const float* bw    = (const float*)d_in[2];   // (8, 9)
    const float* ss    = (const float*)d_in[3];   // (8, 9)
    float* out = (float*)d_out;

    cudaFuncSetAttribute(kan_conv_kernel,
                         cudaFuncAttributeMaxDynamicSharedMemorySize, SMEM_BYTES);

    // 1) compute dup-pair weights into staging, 2) copy into __constant__ bank
    //    (D2D async memcpy — graph-capturable), 3) main kernel reads via LDC.
    prep_kernel<<<1, 296>>>(cheby, bw, ss);
    void* stage_ptr = nullptr;
    cudaGetSymbolAddress(&stage_ptr, g_wstage);
    cudaMemcpyToSymbolAsync(cw, stage_ptr, 296 * sizeof(ull), 0,
                            cudaMemcpyDeviceToDevice, 0);

    const int planes = 16 * 16;                   // B * C
    dim3 grid(planes * (H / TILE_ROWS));          // 4096 blocks
    kan_conv_kernel<<<grid, NTHREADS, SMEM_BYTES>>>(x, out);
}

// round 17
// speedup vs baseline: 1.7905x; 1.1987x over previous
#include <cuda_runtime.h>

#define H 128
#define W 128
#define NCONV 8
#define TILE_ROWS 8
#define FROWS 10          // TILE_ROWS + 2 halo
#define ESTRIDE 66        // entries per (f,row) in Ee/Eo (65 used, padded)
#define NTHREADS 256
#define NWARP 8
#define NTASK (FROWS * 5) // 50 feature tasks (32-wide chunks)

// dynamic smem layout (bytes) — weights/bias in __constant__ (j-pair packed)
#define OFF_EE   0                                   // ull Ee[4][10][66] = 21120  (dup F, even i)
#define OFF_EO   21120                               // ull Eo[4][10][66] = 21120  (dup F, odd i)
#define SMEM_BYTES 42240

typedef unsigned long long ull;

__device__ __forceinline__ ull pk2(float lo, float hi) {
    ull r; asm("mov.b64 %0, {%1, %2};" : "=l"(r) : "f"(lo), "f"(hi)); return r;
}
__device__ __forceinline__ void upk2(ull v, float &lo, float &hi) {
    asm("mov.b64 {%0, %1}, %2;" : "=f"(lo), "=f"(hi) : "l"(v));
}
__device__ __forceinline__ void fma2(ull &d, ull a, ull b) {
    asm("fma.rn.f32x2 %0, %1, %2, %0;" : "+l"(d) : "l"(a), "l"(b));
}
__device__ __forceinline__ float tanh_ap(float x) {
    float r; asm("tanh.approx.f32 %0, %1;" : "=f"(r) : "f"(x)); return r;
}

// constant bank: [0..143] j-pair weights cw[fi*4+jp] = (w_{2jp}, w_{2jp+1}),
// fi = (dy*3+dx)*4 + f;  [144..147] bias pairs.
__constant__ ull cw[148];
__device__   ull g_wstage[148];

// features of one input value: 2 MUFU + a few fma
__device__ __forceinline__ void feats(float xv, float &s, float &t, float &t2, float &t3) {
    t = tanh_ap(xv);                               // tanh
    float th = tanh_ap(0.5f * xv);
    float sg = fmaf(0.5f, th, 0.5f);               // sigmoid(x)
    s  = xv * sg;                                  // silu
    t2 = fmaf(t + t, t, -1.f);                     // T2
    t3 = fmaf(t + t, t2, -t);                      // T3
}

__global__ void prep_kernel(const float* __restrict__ cheby,
                            const float* __restrict__ bw,
                            const float* __restrict__ ss) {
    int idx = threadIdx.x;
    if (idx < 144) {
        int jp  = idx & 3;
        int fi  = idx >> 2;
        int tap = fi >> 2;
        int f   = fi & 3;
        int j0  = jp * 2, j1 = jp * 2 + 1;
        float w0, w1;
        if (f == 0) {
            w0 = bw[j0 * 9 + tap];
            w1 = bw[j1 * 9 + tap];
        } else {
            w0 = cheby[(j0 * 9 + tap) * 4 + f] * ss[j0 * 9 + tap];
            w1 = cheby[(j1 * 9 + tap) * 4 + f] * ss[j1 * 9 + tap];
        }
        g_wstage[idx] = pk2(w0, w1);
    } else if (idx < 148) {
        int jp = idx - 144;
        int j0 = jp * 2, j1 = jp * 2 + 1;
        float s0 = 0.f, s1 = 0.f;
        #pragma unroll
        for (int i = 0; i < 9; i++) {
            s0 += cheby[(j0 * 9 + i) * 4] * ss[j0 * 9 + i];
            s1 += cheby[(j1 * 9 + i) * 4] * ss[j1 * 9 + i];
        }
        g_wstage[idx] = pk2(s0, s1);
    }
}

__global__ void __launch_bounds__(NTHREADS, 5)
kan_conv_kernel(const float* __restrict__ x, float* __restrict__ out)
{
    extern __shared__ char smem_raw[];
    ull* Ee = (ull*)(smem_raw + OFF_EE);      // (F(i),F(i)) for even i, at [f][row][i/2]
    ull* Eo = (ull*)(smem_raw + OFF_EO);      // (F(i),F(i)) for odd  i, at [f][row][(i-1)/2]

    const int tid  = threadIdx.x;
    const int wid  = tid >> 5;
    const int lane = tid & 31;
    const int blk  = blockIdx.x;
    const int bc   = blk >> 4;                    // plane b*C + c (0..255)
    const int r0   = (blk & 15) * TILE_ROWS;      // tile top row

    const float* xp = x + (size_t)bc * (H * W);

    // ---- Phase B1: prefetch all feature-input LDGs (MLP up to 7 per warp) ----
    // task = wid + 8q -> (row, 32-wide chunk c); lane's F index i = 32c + lane.
    float xv[7];
    {
        int row = (wid >= 5) ? 1 : 0;
        int c   = wid - ((wid >= 5) ? 5 : 0);
        #pragma unroll
        for (int q = 0; q < 7; q++) {
            int gr  = r0 - 1 + row;
            int col = (c << 5) + lane - 1;         // i - 1
            xv[q] = 0.f;
            if ((wid + q * 8 < NTASK) & ((unsigned)gr < H) & ((unsigned)col < W))
                xv[q] = xp[(gr << 7) + col];       // W == 128
            row += 1; c += 3;
            if (c >= 5) { c -= 5; row += 1; }
        }
    }

    // ---- Phase B2: features -> duplicated parity smem (no shfl needed) ----
    {
        int c    = wid - ((wid >= 5) ? 5 : 0);
        int rowE = (wid >= 5) ? ESTRIDE : 0;       // row * ESTRIDE, incremental
        #pragma unroll
        for (int q = 0; q < 7; q++) {
            int i = (c << 5) + lane;               // feature index (col = i-1)
            if ((wid + q * 8 < NTASK) && i <= 129) {
                float s, t1, t2, t3;
                feats(xv[q], s, t1, t2, t3);       // x=0 padding -> (0,0,-1,0) ✓
                ull v0 = pk2(s,  s);
                ull v1 = pk2(t1, t1);
                ull v2 = pk2(t2, t2);
                ull v3 = pk2(t3, t3);
                int rb = rowE + (i >> 1);
                if ((i & 1) == 0) {
                    Ee[(0 * FROWS) * ESTRIDE + rb] = v0;
                    Ee[(1 * FROWS) * ESTRIDE + rb] = v1;
                    Ee[(2 * FROWS) * ESTRIDE + rb] = v2;
                    Ee[(3 * FROWS) * ESTRIDE + rb] = v3;
                } else {
                    Eo[(0 * FROWS) * ESTRIDE + rb] = v0;
                    Eo[(1 * FROWS) * ESTRIDE + rb] = v1;
                    Eo[(2 * FROWS) * ESTRIDE + rb] = v2;
                    Eo[(3 * FROWS) * ESTRIDE + rb] = v3;
                }
            }
            c += 3;
            if (c >= 5) { c -= 5; rowE += 2 * ESTRIDE; } else { rowE += ESTRIDE; }
        }
    }
    __syncthreads();

    // ---- Compute: thread -> 2 rows (ty,ty+1), cols {2L,2L+1}, 8 j (4 j-pairs) ----
    // acc lanes = (j_{2jp}, j_{2jp+1}); features duplicated; weights j-paired in cw.
    // win[m] = dup F at i = c0+m : m even -> Ee[base+m/2], m odd -> Eo[base+m/2].
    const int L  = tid & 63;                       // col-pair index, c0 = 2L
    const int ty = (tid >> 6) * 2;                 // local out rows ty, ty+1

    ull acc[4][4];                                 // [jp][r*2+g]
    #pragma unroll
    for (int jp = 0; jp < 4; jp++) {
        ull b = cw[144 + jp];
        acc[jp][0] = b; acc[jp][1] = b; acc[jp][2] = b; acc[jp][3] = b;
    }

    const int tybase = ty * ESTRIDE + L;           // single IMAD; rest immediates

    #pragma unroll
    for (int f = 0; f < 4; f++) {
        ull lo[4], hi[4];
        {   // input rows ty (lo) and ty+1 (hi): dup F at i = c0..c0+3
            int b0 = (f * FROWS) * ESTRIDE + tybase;
            lo[0] = Ee[b0]; lo[1] = Eo[b0]; lo[2] = Ee[b0 + 1]; lo[3] = Eo[b0 + 1];
            int b1 = b0 + ESTRIDE;
            hi[0] = Ee[b1]; hi[1] = Eo[b1]; hi[2] = Ee[b1 + 1]; hi[3] = Eo[b1 + 1];
        }
        #pragma unroll
        for (int dy = 0; dy < 3; dy++) {
            #pragma unroll
            for (int dx = 0; dx < 3; dx++) {
                const int fi = (dy * 3 + dx) * 4 + f;
                const ulonglong2* wp = (const ulonglong2*)&cw[fi * 4];
                ulonglong2 wA = wp[0], wB = wp[1];     // (jp0,jp1), (jp2,jp3)
                ull l0 = lo[dx], l1 = lo[dx + 1];      // row ty+dy, cols c0, c0+1
                ull h0 = hi[dx], h1 = hi[dx + 1];      // row ty+1+dy
                fma2(acc[0][0], l0, wA.x); fma2(acc[0][1], l1, wA.x);
                fma2(acc[0][2], h0, wA.x); fma2(acc[0][3], h1, wA.x);
                fma2(acc[1][0], l0, wA.y); fma2(acc[1][1], l1, wA.y);
                fma2(acc[1][2], h0, wA.y); fma2(acc[1][3], h1, wA.y);
                fma2(acc[2][0], l0, wB.x); fma2(acc[2][1], l1, wB.x);
                fma2(acc[2][2], h0, wB.x); fma2(acc[2][3], h1, wB.x);
                fma2(acc[3][0], l0, wB.y); fma2(acc[3][1], l1, wB.y);
                fma2(acc[3][2], h0, wB.y); fma2(acc[3][3], h1, wB.y);
            }
            if (dy < 2) {                          // roll window: lo <- hi, next row
                lo[0] = hi[0]; lo[1] = hi[1]; lo[2] = hi[2]; lo[3] = hi[3];
                int bn = (f * FROWS + dy + 2) * ESTRIDE + tybase;
                hi[0] = Ee[bn]; hi[1] = Eo[bn]; hi[2] = Ee[bn + 1]; hi[3] = Eo[bn + 1];
            }
        }
    }

    // ---- epilogue: re-pack j-pairs into col-pairs, 16 dense STG.64 ----
    float* ob = out + ((size_t)(bc * NCONV) * H + (r0 + ty)) * W + 2 * L;
    #pragma unroll
    for (int jp = 0; jp < 4; jp++) {
        #pragma unroll
        for (int r = 0; r < 2; r++) {
            float a0l, a0h, a1l, a1h;
            upk2(acc[jp][r * 2 + 0], a0l, a0h);    // cols c0:   (j0, j1)
            upk2(acc[jp][r * 2 + 1], a1l, a1h);    // cols c0+1: (j0, j1)
            ull vj0 = pk2(a0l, a1l);               // plane j=2jp,   cols c0,c0+1
            ull vj1 = pk2(a0h, a1h);               // plane j=2jp+1
            *(ull*)(ob + (size_t)(2 * jp)     * (H * W) + r * W) = vj0;
            *(ull*)(ob + (size_t)(2 * jp + 1) * (H * W) + r * W) = vj1;
        }
    }
}

extern "C" void kernel_launch(void* const* d_in, const int* in_sizes, int n_in,
                              void* d_out, int out_size) {
    const float* x     = (const float*)d_in[0];
    const float* cheby = (const float*)d_in[1];   // (8, 9, 4)
    const float* bw    = (const float*)d_in[2];   // (8, 9)
    const float* ss    = (const float*)d_in[3];   // (8, 9)
    float* out = (float*)d_out;

    cudaFuncSetAttribute(kan_conv_kernel,
                         cudaFuncAttributeMaxDynamicSharedMemorySize, SMEM_BYTES);

    // 1) compute j-pair weights into staging, 2) copy into __constant__ bank
    //    (D2D async memcpy — graph-capturable), 3) main kernel reads via LDC.
    prep_kernel<<<1, 148>>>(cheby, bw, ss);
    void* stage_ptr = nullptr;
    cudaGetSymbolAddress(&stage_ptr, g_wstage);
    cudaMemcpyToSymbolAsync(cw, stage_ptr, 148 * sizeof(ull), 0,
                            cudaMemcpyDeviceToDevice, 0);

    const int planes = 16 * 16;                   // B * C
    dim3 grid(planes * (H / TILE_ROWS));          // 4096 blocks
    kan_conv_kernel<<<grid, NTHREADS, SMEM_BYTES>>>(x, out);
}